// round 3
// baseline (speedup 1.0000x reference)
#include <cuda_runtime.h>
#include <math.h>

// ---------------- problem constants ----------------
#define BATCH 2
#define DDIM  8
#define CH    256
#define SPA   84          // both spatial dims
#define NHEAD 8
#define HDIM  32
#define NTOK  98          // 2*7*7 tokens per window
#define NWINB 576         // windows per batch (4*12*12)
#define BWIN  1152        // BATCH*NWINB
#define TOK   112896      // BATCH*DDIM*SPA*SPA
#define HID   1024

// ---------------- scratch (device globals; no allocation allowed) ----------
__device__ float g_xp  [(size_t)TOK * CH];   // transposed input (token-major), residual shortcut
__device__ float g_xw  [(size_t)TOK * CH];   // LN1 + shift + window partition
__device__ float g_qkv [(size_t)TOK * 3*CH];
__device__ float g_att [(size_t)TOK * CH];   // attention output (window-row layout)
__device__ float g_xres[(size_t)TOK * CH];   // shortcut + proj (token layout)
__device__ float g_h2  [(size_t)TOK * CH];   // LN2 output
__device__ float g_mlp [(size_t)TOK * HID];  // fc1+gelu output
__device__ float g_y   [(size_t)TOK * CH];   // final (token layout)

// window row m -> token index (window reverse + roll(+shift)); also used by LN1 source gather
__device__ __forceinline__ int row_to_token(int m)
{
    int bb = m / 56448;  int r  = m - bb * 56448;   // 56448 = 576*98
    int win = r / 98;    int n  = r - win * 98;
    int dw = win / 144;  int r2 = win - dw * 144;
    int hw = r2 / 12;    int ww = r2 - hw * 12;
    int td = n / 49;     int r3 = n - td * 49;
    int th = r3 / 7;     int tw = r3 - th * 7;
    int d = (dw * 2 + td + 1) & 7;
    int h = hw * 7 + th + 3; if (h >= SPA) h -= SPA;
    int w = ww * 7 + tw + 3; if (w >= SPA) w -= SPA;
    return ((bb * DDIM + d) * SPA + h) * SPA + w;
}

// ---------------- transpose in: x(B,D,C,W,H) -> xp(token, C) -----------------
// token t = ((b*8+d)*84 + h)*84 + w  ;  xp[t,c] = x[b,d,c,w,h]
__global__ void transpose_in_kernel(const float* __restrict__ x, float* __restrict__ xp)
{
    __shared__ float tile[32][33];
    int ct = blockIdx.x & 7, ht = blockIdx.x >> 3;   // 8 c-tiles, 3 h-tiles
    int w  = blockIdx.y;
    int bd = blockIdx.z;
    int h0 = ht * 32, c0 = ct * 32;
    int tx = threadIdx.x, ty = threadIdx.y;
    const float* xb = x + (size_t)bd * CH * (SPA*SPA);
#pragma unroll
    for (int i = 0; i < 32; i += 8) {
        int c = c0 + ty + i; int h = h0 + tx;
        if (h < SPA) tile[ty + i][tx] = xb[(size_t)c * (SPA*SPA) + w * SPA + h];
    }
    __syncthreads();
    float* xpb = xp + (size_t)bd * (SPA*SPA) * CH;
#pragma unroll
    for (int i = 0; i < 32; i += 8) {
        int h = h0 + ty + i; int c = c0 + tx;
        if (h < SPA) xpb[((size_t)h * SPA + w) * CH + c] = tile[tx][ty + i];
    }
}

// ---------------- transpose out: y(token,C) -> out(B,D,C,W,H) ----------------
__global__ void transpose_out_kernel(const float* __restrict__ y, float* __restrict__ o)
{
    __shared__ float tile[32][33];
    int ct = blockIdx.x & 7, ht = blockIdx.x >> 3;
    int w  = blockIdx.y;
    int bd = blockIdx.z;
    int h0 = ht * 32, c0 = ct * 32;
    int tx = threadIdx.x, ty = threadIdx.y;
    const float* yb = y + (size_t)bd * (SPA*SPA) * CH;
#pragma unroll
    for (int i = 0; i < 32; i += 8) {
        int h = h0 + ty + i; int c = c0 + tx;
        if (h < SPA) tile[ty + i][tx] = yb[((size_t)h * SPA + w) * CH + c];
    }
    __syncthreads();
    float* ob = o + (size_t)bd * CH * (SPA*SPA);
#pragma unroll
    for (int i = 0; i < 32; i += 8) {
        int c = c0 + ty + i; int h = h0 + tx;
        if (h < SPA) ob[(size_t)c * (SPA*SPA) + w * SPA + h] = tile[tx][ty + i];
    }
}

// ---------------- LayerNorm (warp per token, C=256) --------------------------
// MAP=true : output row m gathers from shifted source token (LN1 + roll + window partition)
// MAP=false: identity rows (LN2)
template <bool MAP>
__global__ void ln_kernel(const float* __restrict__ src_buf, const float* __restrict__ g,
                          const float* __restrict__ b, float* __restrict__ dst_buf)
{
    int warp = threadIdx.x >> 5, lane = threadIdx.x & 31;
    int m = blockIdx.x * 8 + warp;
    int t = MAP ? row_to_token(m) : m;
    const float* src = src_buf + (size_t)t * CH;
    float4 v0 = *(const float4*)(src + lane * 4);
    float4 v1 = *(const float4*)(src + 128 + lane * 4);
    float s = v0.x + v0.y + v0.z + v0.w + v1.x + v1.y + v1.z + v1.w;
    float q = v0.x*v0.x + v0.y*v0.y + v0.z*v0.z + v0.w*v0.w
            + v1.x*v1.x + v1.y*v1.y + v1.z*v1.z + v1.w*v1.w;
#pragma unroll
    for (int o = 16; o; o >>= 1) {
        s += __shfl_xor_sync(0xffffffffu, s, o);
        q += __shfl_xor_sync(0xffffffffu, q, o);
    }
    float mean = s * (1.0f / 256.0f);
    float var  = q * (1.0f / 256.0f) - mean * mean;
    float rstd = rsqrtf(var + 1e-5f);
    float4 gg0 = *(const float4*)(g + lane * 4),  gg1 = *(const float4*)(g + 128 + lane * 4);
    float4 bb0 = *(const float4*)(b + lane * 4),  bb1 = *(const float4*)(b + 128 + lane * 4);
    float4 o0, o1;
    o0.x = (v0.x - mean) * rstd * gg0.x + bb0.x;
    o0.y = (v0.y - mean) * rstd * gg0.y + bb0.y;
    o0.z = (v0.z - mean) * rstd * gg0.z + bb0.z;
    o0.w = (v0.w - mean) * rstd * gg0.w + bb0.w;
    o1.x = (v1.x - mean) * rstd * gg1.x + bb1.x;
    o1.y = (v1.y - mean) * rstd * gg1.y + bb1.y;
    o1.z = (v1.z - mean) * rstd * gg1.z + bb1.z;
    o1.w = (v1.w - mean) * rstd * gg1.w + bb1.w;
    float* dst = dst_buf + (size_t)m * CH;
    *(float4*)(dst + lane * 4) = o0;
    *(float4*)(dst + 128 + lane * 4) = o1;
}

// ---------------- SGEMM: C = A(MxK) * B(NxK)^T, 128x128x8, 256 thr ----------
// MODE 0: plain store (qkv)
// MODE 1: + bias + residual, scattered to token layout (proj): C=xres, res=xp
// MODE 2: + bias + exact GELU (fc1)
// MODE 3: + bias + residual row-aligned (fc2): res=xres
__device__ __forceinline__ float gelu_exact(float v)
{
    return 0.5f * v * (1.0f + erff(v * 0.70710678118654752f));
}

template <int MODE>
__global__ __launch_bounds__(256, 2)
void sgemm_kernel(const float* __restrict__ A, const float* __restrict__ B,
                  const float* __restrict__ bias, const float* __restrict__ res,
                  float* __restrict__ C, int M, int N, int K)
{
    __shared__ __align__(16) float As[8][132];
    __shared__ __align__(16) float Bs[8][132];
    const int tid = threadIdx.x;
    const int bn = blockIdx.x, bm = blockIdx.y;
    const int lrow = tid >> 1;
    const int lk   = (tid & 1) * 4;
    const float* Ap = A + (size_t)(bm * 128 + lrow) * K + lk;
    const float* Bp = B + (size_t)(bn * 128 + lrow) * K + lk;
    const int tx = tid & 15, ty = tid >> 4;

    float acc[8][8];
#pragma unroll
    for (int i = 0; i < 8; i++)
#pragma unroll
        for (int j = 0; j < 8; j++) acc[i][j] = 0.0f;

    float4 av = *(const float4*)Ap;
    float4 bv = *(const float4*)Bp;

    for (int k0 = 0; k0 < K; k0 += 8) {
        As[lk + 0][lrow] = av.x; As[lk + 1][lrow] = av.y;
        As[lk + 2][lrow] = av.z; As[lk + 3][lrow] = av.w;
        Bs[lk + 0][lrow] = bv.x; Bs[lk + 1][lrow] = bv.y;
        Bs[lk + 2][lrow] = bv.z; Bs[lk + 3][lrow] = bv.w;
        __syncthreads();
        if (k0 + 8 < K) {
            av = *(const float4*)(Ap + k0 + 8);
            bv = *(const float4*)(Bp + k0 + 8);
        }
#pragma unroll
        for (int k = 0; k < 8; k++) {
            float af[8], bf[8];
            *(float4*)(af)     = *(const float4*)(&As[k][ty * 8]);
            *(float4*)(af + 4) = *(const float4*)(&As[k][ty * 8 + 4]);
            *(float4*)(bf)     = *(const float4*)(&Bs[k][tx * 8]);
            *(float4*)(bf + 4) = *(const float4*)(&Bs[k][tx * 8 + 4]);
#pragma unroll
            for (int i = 0; i < 8; i++)
#pragma unroll
                for (int j = 0; j < 8; j++)
                    acc[i][j] += af[i] * bf[j];
        }
        __syncthreads();
    }

    const int gm0 = bm * 128 + ty * 8;
    const int gn0 = bn * 128 + tx * 8;
    float bb[8];
    if (MODE != 0) {
#pragma unroll
        for (int j = 0; j < 8; j++) bb[j] = bias[gn0 + j];
    }

    if (MODE == 0) {
#pragma unroll
        for (int i = 0; i < 8; i++) {
            float* dst = C + (size_t)(gm0 + i) * N + gn0;
            float4 v0 = make_float4(acc[i][0], acc[i][1], acc[i][2], acc[i][3]);
            float4 v1 = make_float4(acc[i][4], acc[i][5], acc[i][6], acc[i][7]);
            *(float4*)dst = v0; *(float4*)(dst + 4) = v1;
        }
    } else if (MODE == 1) {
        for (int i = 0; i < 8; i++) {
            int t = row_to_token(gm0 + i);
            float* dst = C + (size_t)t * CH + gn0;
            const float* rs = res + (size_t)t * CH + gn0;
#pragma unroll
            for (int j = 0; j < 8; j++) dst[j] = acc[i][j] + bb[j] + rs[j];
        }
    } else if (MODE == 2) {
#pragma unroll
        for (int i = 0; i < 8; i++) {
            float* dst = C + (size_t)(gm0 + i) * N + gn0;
#pragma unroll
            for (int j = 0; j < 8; j++) dst[j] = gelu_exact(acc[i][j] + bb[j]);
        }
    } else {
#pragma unroll
        for (int i = 0; i < 8; i++) {
            float* dst = C + (size_t)(gm0 + i) * N + gn0;
            const float* rs = res + (size_t)(gm0 + i) * N + gn0;
#pragma unroll
            for (int j = 0; j < 8; j++) dst[j] = acc[i][j] + bb[j] + rs[j];
        }
    }
}

// ---------------- windowed attention -----------------------------------------
// grid.x = BWIN*NHEAD ; 128 threads ; dynamic smem: q/k/v [98][33], scores [98][101], bias [507]
#define SPSTR   101
#define SMF_Q   0
#define SMF_K   (98 * 33)
#define SMF_V   (2 * 98 * 33)
#define SMF_P   (3 * 98 * 33)
#define SMF_B   (3 * 98 * 33 + 98 * SPSTR)
#define SMF_TOT (3 * 98 * 33 + 98 * SPSTR + 507)

__global__ void attn_kernel(const float* __restrict__ qkv, const float* __restrict__ rpb,
                            float* __restrict__ out)
{
    extern __shared__ float sm[];
    float* sq = sm + SMF_Q;
    float* sk = sm + SMF_K;
    float* sv = sm + SMF_V;
    float* sp = sm + SMF_P;      // [98][SPSTR]
    float* sbias = sm + SMF_B;   // [507]
    __shared__ signed char std_[98], sth[98], stw[98], scnt[98];

    int bh   = blockIdx.x;
    int head = bh & 7;
    int bw   = bh >> 3;           // window row block in [0, 1152)
    int win  = bw % NWINB;
    int dw = win / 144; int r2 = win - dw * 144;
    int hw = r2 / 12;   int ww = r2 - hw * 12;

    int tid = threadIdx.x;
    const float* base = qkv + (size_t)bw * NTOK * (3 * CH);
    const float scale = 0.17677669529663687f;  // 32^-0.5

    for (int idx = tid; idx < NTOK * HDIM; idx += 128) {
        int n = idx >> 5, d = idx & 31;
        const float* rowp = base + (size_t)n * (3 * CH) + head * HDIM + d;
        sq[n * 33 + d] = rowp[0] * scale;
        sk[n * 33 + d] = rowp[CH];
        sv[n * 33 + d] = rowp[2 * CH];
    }
    for (int idx = tid; idx < 507; idx += 128) sbias[idx] = rpb[idx * NHEAD + head];
    for (int n = tid; n < NTOK; n += 128) {
        int td = n / 49; int r = n - td * 49; int th = r / 7; int tw = r - th * 7;
        std_[n] = (signed char)td; sth[n] = (signed char)th; stw[n] = (signed char)tw;
        int ds = dw * 2 + td, hs = hw * 7 + th, ws = ww * 7 + tw;
        int rd = ds < 6 ? 0 : (ds < 7 ? 1 : 2);
        int rh = hs < 77 ? 0 : (hs < 81 ? 1 : 2);
        int rw = ws < 77 ? 0 : (ws < 81 ? 1 : 2);
        scnt[n] = (signed char)(rd * 9 + rh * 3 + rw);
    }
    __syncthreads();

    if (tid < NTOK) {
        float qr[HDIM];
#pragma unroll
        for (int d = 0; d < HDIM; d++) qr[d] = sq[tid * 33 + d];
        int tdi = std_[tid], thi = sth[tid], twi = stw[tid], ci = scnt[tid];

        float mx = -1e30f;
        for (int j = 0; j < NTOK; j++) {
            const float* kj = sk + j * 33;
            float s0 = 0.f, s1 = 0.f, s2 = 0.f, s3 = 0.f;
#pragma unroll
            for (int d = 0; d < HDIM; d += 4) {
                s0 += qr[d + 0] * kj[d + 0];
                s1 += qr[d + 1] * kj[d + 1];
                s2 += qr[d + 2] * kj[d + 2];
                s3 += qr[d + 3] * kj[d + 3];
            }
            float s = (s0 + s1) + (s2 + s3);
            int bidx = (tdi - std_[j] + 1) * 169 + (thi - sth[j] + 6) * 13 + (twi - stw[j] + 6);
            s += sbias[bidx];
            if (ci != scnt[j]) s -= 100.0f;
            sp[tid * SPSTR + j] = s;
            mx = fmaxf(mx, s);
        }
        float sum = 0.f;
        for (int j = 0; j < NTOK; j++) {
            float e = __expf(sp[tid * SPSTR + j] - mx);
            sp[tid * SPSTR + j] = e;
            sum += e;
        }
        float inv = 1.0f / sum;
        float o[HDIM];
#pragma unroll
        for (int d = 0; d < HDIM; d++) o[d] = 0.f;
        for (int j = 0; j < NTOK; j++) {
            float p = sp[tid * SPSTR + j] * inv;
            const float* vj = sv + j * 33;
#pragma unroll
            for (int d = 0; d < HDIM; d++) o[d] += p * vj[d];
        }
        float* op = out + ((size_t)bw * NTOK + tid) * CH + head * HDIM;
#pragma unroll
        for (int d = 0; d < HDIM; d += 4)
            *(float4*)(op + d) = make_float4(o[d], o[d + 1], o[d + 2], o[d + 3]);
    }
}

// ---------------- launch ------------------------------------------------------
extern "C" void kernel_launch(void* const* d_in, const int* in_sizes, int n_in,
                              void* d_out, int out_size)
{
    const float* x     = (const float*)d_in[0];
    const float* n1g   = (const float*)d_in[1];
    const float* n1b   = (const float*)d_in[2];
    const float* qkvw  = (const float*)d_in[3];
    const float* rpb   = (const float*)d_in[4];
    const float* projw = (const float*)d_in[5];
    const float* projb = (const float*)d_in[6];
    const float* n2g   = (const float*)d_in[7];
    const float* n2b   = (const float*)d_in[8];
    const float* fc1w  = (const float*)d_in[9];
    const float* fc1b  = (const float*)d_in[10];
    const float* fc2w  = (const float*)d_in[11];
    const float* fc2b  = (const float*)d_in[12];
    float* out = (float*)d_out;

    void *pxp, *pxw, *pqkv, *patt, *pxres, *ph2, *pmlp, *py;
    cudaGetSymbolAddress(&pxp,  g_xp);
    cudaGetSymbolAddress(&pxw,  g_xw);
    cudaGetSymbolAddress(&pqkv, g_qkv);
    cudaGetSymbolAddress(&patt, g_att);
    cudaGetSymbolAddress(&pxres,g_xres);
    cudaGetSymbolAddress(&ph2,  g_h2);
    cudaGetSymbolAddress(&pmlp, g_mlp);
    cudaGetSymbolAddress(&py,   g_y);
    float* xp   = (float*)pxp;
    float* xw   = (float*)pxw;
    float* qkv  = (float*)pqkv;
    float* att  = (float*)patt;
    float* xres = (float*)pxres;
    float* h2   = (float*)ph2;
    float* mlp  = (float*)pmlp;
    float* y    = (float*)py;

    dim3 tb(32, 8);
    dim3 tg(24, 84, 16);

    transpose_in_kernel<<<tg, tb>>>(x, xp);
    ln_kernel<true><<<TOK / 8, 256>>>(xp, n1g, n1b, xw);

    dim3 gq(768 / 128, TOK / 128);
    sgemm_kernel<0><<<gq, 256>>>(xw, qkvw, nullptr, nullptr, qkv, TOK, 768, 256);

    int smem_attn = SMF_TOT * (int)sizeof(float);
    cudaFuncSetAttribute(attn_kernel, cudaFuncAttributeMaxDynamicSharedMemorySize, smem_attn);
    attn_kernel<<<BWIN * NHEAD, 128, smem_attn>>>(qkv, rpb, att);

    dim3 gp(256 / 128, TOK / 128);
    sgemm_kernel<1><<<gp, 256>>>(att, projw, projb, xp, xres, TOK, 256, 256);

    ln_kernel<false><<<TOK / 8, 256>>>(xres, n2g, n2b, h2);

    dim3 g1(1024 / 128, TOK / 128);
    sgemm_kernel<2><<<g1, 256>>>(h2, fc1w, fc1b, nullptr, mlp, TOK, 1024, 256);

    dim3 g2(256 / 128, TOK / 128);
    sgemm_kernel<3><<<g2, 256>>>(mlp, fc2w, fc2b, xres, y, TOK, 256, 1024);

    transpose_out_kernel<<<tg, tb>>>(y, out);
}

// round 5
// speedup vs baseline: 1.5307x; 1.5307x over previous
#include <cuda_runtime.h>
#include <math.h>
#include <stdint.h>

// ---------------- problem constants ----------------
#define BATCH 2
#define DDIM  8
#define CH    256
#define SPA   84
#define NHEAD 8
#define HDIM  32
#define NTOK  98
#define NWINB 576
#define BWIN  1152
#define TOK   112896
#define HID   1024

// ---------------- scratch ----------------
__device__ float g_xp  [(size_t)TOK * CH];
__device__ float g_xw  [(size_t)TOK * CH];
__device__ float g_qkv [(size_t)TOK * 3*CH];
__device__ float g_att [(size_t)TOK * CH];
__device__ float g_xres[(size_t)TOK * CH];
__device__ float g_h2  [(size_t)TOK * CH];
__device__ float g_mlp [(size_t)TOK * HID];
__device__ float g_y   [(size_t)TOK * CH];

__device__ __forceinline__ int row_to_token(int m)
{
    int bb = m / 56448;  int r  = m - bb * 56448;
    int win = r / 98;    int n  = r - win * 98;
    int dw = win / 144;  int r2 = win - dw * 144;
    int hw = r2 / 12;    int ww = r2 - hw * 12;
    int td = n / 49;     int r3 = n - td * 49;
    int th = r3 / 7;     int tw = r3 - th * 7;
    int d = (dw * 2 + td + 1) & 7;
    int h = hw * 7 + th + 3; if (h >= SPA) h -= SPA;
    int w = ww * 7 + tw + 3; if (w >= SPA) w -= SPA;
    return ((bb * DDIM + d) * SPA + h) * SPA + w;
}

// ---------------- transposes ----------------
__global__ void transpose_in_kernel(const float* __restrict__ x, float* __restrict__ xp)
{
    __shared__ float tile[32][33];
    int ct = blockIdx.x & 7, ht = blockIdx.x >> 3;
    int w  = blockIdx.y;
    int bd = blockIdx.z;
    int h0 = ht * 32, c0 = ct * 32;
    int tx = threadIdx.x, ty = threadIdx.y;
    const float* xb = x + (size_t)bd * CH * (SPA*SPA);
#pragma unroll
    for (int i = 0; i < 32; i += 8) {
        int c = c0 + ty + i; int h = h0 + tx;
        if (h < SPA) tile[ty + i][tx] = xb[(size_t)c * (SPA*SPA) + w * SPA + h];
    }
    __syncthreads();
    float* xpb = xp + (size_t)bd * (SPA*SPA) * CH;
#pragma unroll
    for (int i = 0; i < 32; i += 8) {
        int h = h0 + ty + i; int c = c0 + tx;
        if (h < SPA) xpb[((size_t)h * SPA + w) * CH + c] = tile[tx][ty + i];
    }
}

__global__ void transpose_out_kernel(const float* __restrict__ y, float* __restrict__ o)
{
    __shared__ float tile[32][33];
    int ct = blockIdx.x & 7, ht = blockIdx.x >> 3;
    int w  = blockIdx.y;
    int bd = blockIdx.z;
    int h0 = ht * 32, c0 = ct * 32;
    int tx = threadIdx.x, ty = threadIdx.y;
    const float* yb = y + (size_t)bd * (SPA*SPA) * CH;
#pragma unroll
    for (int i = 0; i < 32; i += 8) {
        int h = h0 + ty + i; int c = c0 + tx;
        if (h < SPA) tile[ty + i][tx] = yb[((size_t)h * SPA + w) * CH + c];
    }
    __syncthreads();
    float* ob = o + (size_t)bd * CH * (SPA*SPA);
#pragma unroll
    for (int i = 0; i < 32; i += 8) {
        int c = c0 + ty + i; int h = h0 + tx;
        if (h < SPA) ob[(size_t)c * (SPA*SPA) + w * SPA + h] = tile[tx][ty + i];
    }
}

// ---------------- LayerNorm ----------------
template <bool MAP>
__global__ void ln_kernel(const float* __restrict__ src_buf, const float* __restrict__ g,
                          const float* __restrict__ b, float* __restrict__ dst_buf)
{
    int warp = threadIdx.x >> 5, lane = threadIdx.x & 31;
    int m = blockIdx.x * 8 + warp;
    int t = MAP ? row_to_token(m) : m;
    const float* src = src_buf + (size_t)t * CH;
    float4 v0 = *(const float4*)(src + lane * 4);
    float4 v1 = *(const float4*)(src + 128 + lane * 4);
    float s = v0.x + v0.y + v0.z + v0.w + v1.x + v1.y + v1.z + v1.w;
    float q = v0.x*v0.x + v0.y*v0.y + v0.z*v0.z + v0.w*v0.w
            + v1.x*v1.x + v1.y*v1.y + v1.z*v1.z + v1.w*v1.w;
#pragma unroll
    for (int o = 16; o; o >>= 1) {
        s += __shfl_xor_sync(0xffffffffu, s, o);
        q += __shfl_xor_sync(0xffffffffu, q, o);
    }
    float mean = s * (1.0f / 256.0f);
    float var  = q * (1.0f / 256.0f) - mean * mean;
    float rstd = rsqrtf(var + 1e-5f);
    float4 gg0 = *(const float4*)(g + lane * 4),  gg1 = *(const float4*)(g + 128 + lane * 4);
    float4 bb0 = *(const float4*)(b + lane * 4),  bb1 = *(const float4*)(b + 128 + lane * 4);
    float4 o0, o1;
    o0.x = (v0.x - mean) * rstd * gg0.x + bb0.x;
    o0.y = (v0.y - mean) * rstd * gg0.y + bb0.y;
    o0.z = (v0.z - mean) * rstd * gg0.z + bb0.z;
    o0.w = (v0.w - mean) * rstd * gg0.w + bb0.w;
    o1.x = (v1.x - mean) * rstd * gg1.x + bb1.x;
    o1.y = (v1.y - mean) * rstd * gg1.y + bb1.y;
    o1.z = (v1.z - mean) * rstd * gg1.z + bb1.z;
    o1.w = (v1.w - mean) * rstd * gg1.w + bb1.w;
    float* dst = dst_buf + (size_t)m * CH;
    *(float4*)(dst + lane * 4) = o0;
    *(float4*)(dst + 128 + lane * 4) = o1;
}

// ---------------- tf32 tensor-core GEMM: C = A(MxK) * B(NxK)^T ---------------
__device__ __forceinline__ uint32_t f2tf(float f)
{
    uint32_t r;
    asm("cvt.rna.tf32.f32 %0, %1;" : "=r"(r) : "f"(f));
    return r;
}

__device__ __forceinline__ void mma_tf32(float4& d, const uint32_t a[4], const uint32_t b[2])
{
    asm volatile(
        "mma.sync.aligned.m16n8k8.row.col.f32.tf32.tf32.f32 "
        "{%0,%1,%2,%3}, {%4,%5,%6,%7}, {%8,%9}, {%0,%1,%2,%3};"
        : "+f"(d.x), "+f"(d.y), "+f"(d.z), "+f"(d.w)
        : "r"(a[0]), "r"(a[1]), "r"(a[2]), "r"(a[3]), "r"(b[0]), "r"(b[1]));
}

__device__ __forceinline__ float gelu_exact(float v)
{
    return 0.5f * v * (1.0f + erff(v * 0.70710678118654752f));
}

// 128x128x16 tile, 256 threads, 8 warps each 32x64.
// MODE 0: plain (qkv)  1: bias+residual scattered (proj)  2: bias+gelu (fc1)  3: bias+residual (fc2)
template <int MODE>
__global__ __launch_bounds__(256, 2)
void tgemm_kernel(const float* __restrict__ A, const float* __restrict__ B,
                  const float* __restrict__ bias, const float* __restrict__ res,
                  float* __restrict__ C, int M, int N, int K)
{
    __shared__ uint32_t As[16][136];
    __shared__ uint32_t Bs[16][136];
    const int tid = threadIdx.x;
    const int bn = blockIdx.x, bm = blockIdx.y;
    const int srow = tid & 127;
    const int skb  = (tid >> 7) * 8;
    const float* Ap = A + (size_t)(bm * 128 + srow) * K + skb;
    const float* Bp = B + (size_t)(bn * 128 + srow) * K + skb;

    const int wid  = tid >> 5;
    const int lane = tid & 31;
    const int gid  = lane >> 2;       // 0..7
    const int tig  = lane & 3;        // 0..3
    const int wm   = (wid & 3) * 32;
    const int wn   = (wid >> 2) * 64;

    float4 acc[2][8];
#pragma unroll
    for (int i = 0; i < 2; i++)
#pragma unroll
        for (int j = 0; j < 8; j++) acc[i][j] = make_float4(0.f, 0.f, 0.f, 0.f);

    float4 av0 = *(const float4*)(Ap);
    float4 av1 = *(const float4*)(Ap + 4);
    float4 bv0 = *(const float4*)(Bp);
    float4 bv1 = *(const float4*)(Bp + 4);

    for (int k0 = 0; k0 < K; k0 += 16) {
        As[skb + 0][srow] = f2tf(av0.x); As[skb + 1][srow] = f2tf(av0.y);
        As[skb + 2][srow] = f2tf(av0.z); As[skb + 3][srow] = f2tf(av0.w);
        As[skb + 4][srow] = f2tf(av1.x); As[skb + 5][srow] = f2tf(av1.y);
        As[skb + 6][srow] = f2tf(av1.z); As[skb + 7][srow] = f2tf(av1.w);
        Bs[skb + 0][srow] = f2tf(bv0.x); Bs[skb + 1][srow] = f2tf(bv0.y);
        Bs[skb + 2][srow] = f2tf(bv0.z); Bs[skb + 3][srow] = f2tf(bv0.w);
        Bs[skb + 4][srow] = f2tf(bv1.x); Bs[skb + 5][srow] = f2tf(bv1.y);
        Bs[skb + 6][srow] = f2tf(bv1.z); Bs[skb + 7][srow] = f2tf(bv1.w);
        __syncthreads();
        if (k0 + 16 < K) {
            av0 = *(const float4*)(Ap + k0 + 16);
            av1 = *(const float4*)(Ap + k0 + 20);
            bv0 = *(const float4*)(Bp + k0 + 16);
            bv1 = *(const float4*)(Bp + k0 + 20);
        }
#pragma unroll
        for (int ks = 0; ks < 16; ks += 8) {
            uint32_t af[2][4];
#pragma unroll
            for (int mi = 0; mi < 2; mi++) {
                int m = wm + mi * 16 + gid;
                af[mi][0] = As[ks + tig][m];
                af[mi][1] = As[ks + tig][m + 8];
                af[mi][2] = As[ks + tig + 4][m];
                af[mi][3] = As[ks + tig + 4][m + 8];
            }
            uint32_t bf[8][2];
#pragma unroll
            for (int ni = 0; ni < 8; ni++) {
                int n = wn + ni * 8 + gid;
                bf[ni][0] = Bs[ks + tig][n];
                bf[ni][1] = Bs[ks + tig + 4][n];
            }
#pragma unroll
            for (int mi = 0; mi < 2; mi++)
#pragma unroll
                for (int ni = 0; ni < 8; ni++)
                    mma_tf32(acc[mi][ni], af[mi], bf[ni]);
        }
        __syncthreads();
    }

    // ---------------- epilogue ----------------
    if (MODE == 1) {
        int tok[2][2];
#pragma unroll
        for (int mi = 0; mi < 2; mi++) {
            int r = bm * 128 + wm + mi * 16 + gid;
            tok[mi][0] = row_to_token(r);
            tok[mi][1] = row_to_token(r + 8);
        }
#pragma unroll
        for (int mi = 0; mi < 2; mi++)
#pragma unroll
            for (int ni = 0; ni < 8; ni++) {
                int c = bn * 128 + wn + ni * 8 + 2 * tig;
                float bx = bias[c], by = bias[c + 1];
                float4 a = acc[mi][ni];
                {
                    int t = tok[mi][0];
                    float* d = C + (size_t)t * CH + c;
                    const float* rs = res + (size_t)t * CH + c;
                    d[0] = a.x + bx + rs[0];
                    d[1] = a.y + by + rs[1];
                }
                {
                    int t = tok[mi][1];
                    float* d = C + (size_t)t * CH + c;
                    const float* rs = res + (size_t)t * CH + c;
                    d[0] = a.z + bx + rs[0];
                    d[1] = a.w + by + rs[1];
                }
            }
    } else {
#pragma unroll
        for (int mi = 0; mi < 2; mi++)
#pragma unroll
            for (int ni = 0; ni < 8; ni++) {
                int r = bm * 128 + wm + mi * 16 + gid;
                int c = bn * 128 + wn + ni * 8 + 2 * tig;
                float4 a = acc[mi][ni];
                if (MODE == 0) {
                    *(float2*)(C + (size_t)r * N + c)       = make_float2(a.x, a.y);
                    *(float2*)(C + (size_t)(r + 8) * N + c) = make_float2(a.z, a.w);
                } else if (MODE == 2) {
                    float bx = bias[c], by = bias[c + 1];
                    *(float2*)(C + (size_t)r * N + c) =
                        make_float2(gelu_exact(a.x + bx), gelu_exact(a.y + by));
                    *(float2*)(C + (size_t)(r + 8) * N + c) =
                        make_float2(gelu_exact(a.z + bx), gelu_exact(a.w + by));
                } else {  // MODE 3
                    float bx = bias[c], by = bias[c + 1];
                    const float* r0 = res + (size_t)r * N + c;
                    const float* r1 = res + (size_t)(r + 8) * N + c;
                    *(float2*)(C + (size_t)r * N + c) =
                        make_float2(a.x + bx + r0[0], a.y + by + r0[1]);
                    *(float2*)(C + (size_t)(r + 8) * N + c) =
                        make_float2(a.z + bx + r1[0], a.w + by + r1[1]);
                }
            }
    }
}

// ---------------- windowed attention (online softmax, no score buffer) -------
#define SMF_Q   0
#define SMF_K   (98 * 33)
#define SMF_V   (2 * 98 * 33)
#define SMF_B   (3 * 98 * 33)
#define SMF_TOT (3 * 98 * 33 + 507)

__global__ void attn_kernel(const float* __restrict__ qkv, const float* __restrict__ rpb,
                            float* __restrict__ out)
{
    extern __shared__ float sm[];
    float* sq = sm + SMF_Q;
    float* sk = sm + SMF_K;
    float* sv = sm + SMF_V;
    float* sbias = sm + SMF_B;
    __shared__ signed char std_[98], sth[98], stw[98], scnt[98];

    int bh   = blockIdx.x;
    int head = bh & 7;
    int bw   = bh >> 3;
    int win  = bw % NWINB;
    int dw = win / 144; int r2 = win - dw * 144;
    int hw = r2 / 12;   int ww = r2 - hw * 12;

    int tid = threadIdx.x;
    const float* base = qkv + (size_t)bw * NTOK * (3 * CH);
    const float scale = 0.17677669529663687f;

    for (int idx = tid; idx < NTOK * HDIM; idx += 128) {
        int n = idx >> 5, d = idx & 31;
        const float* rowp = base + (size_t)n * (3 * CH) + head * HDIM + d;
        sq[n * 33 + d] = rowp[0] * scale;
        sk[n * 33 + d] = rowp[CH];
        sv[n * 33 + d] = rowp[2 * CH];
    }
    for (int idx = tid; idx < 507; idx += 128) sbias[idx] = rpb[idx * NHEAD + head];
    for (int n = tid; n < NTOK; n += 128) {
        int td = n / 49; int r = n - td * 49; int th = r / 7; int tw = r - th * 7;
        std_[n] = (signed char)td; sth[n] = (signed char)th; stw[n] = (signed char)tw;
        int ds = dw * 2 + td, hs = hw * 7 + th, ws = ww * 7 + tw;
        int rd = ds < 6 ? 0 : (ds < 7 ? 1 : 2);
        int rh = hs < 77 ? 0 : (hs < 81 ? 1 : 2);
        int rw = ws < 77 ? 0 : (ws < 81 ? 1 : 2);
        scnt[n] = (signed char)(rd * 9 + rh * 3 + rw);
    }
    __syncthreads();

    if (tid < NTOK) {
        float qr[HDIM];
#pragma unroll
        for (int d = 0; d < HDIM; d++) qr[d] = sq[tid * 33 + d];
        int tdi = std_[tid], thi = sth[tid], twi = stw[tid], ci = scnt[tid];

        float mx = -1e30f, sum = 0.f;
        float o[HDIM];
#pragma unroll
        for (int d = 0; d < HDIM; d++) o[d] = 0.f;

        for (int j = 0; j < NTOK; j++) {
            const float* kj = sk + j * 33;
            float s0 = 0.f, s1 = 0.f, s2 = 0.f, s3 = 0.f;
#pragma unroll
            for (int d = 0; d < HDIM; d += 4) {
                s0 += qr[d + 0] * kj[d + 0];
                s1 += qr[d + 1] * kj[d + 1];
                s2 += qr[d + 2] * kj[d + 2];
                s3 += qr[d + 3] * kj[d + 3];
            }
            float s = (s0 + s1) + (s2 + s3);
            int bidx = (tdi - std_[j] + 1) * 169 + (thi - sth[j] + 6) * 13 + (twi - stw[j] + 6);
            s += sbias[bidx];
            if (ci != scnt[j]) s -= 100.0f;

            float nm   = fmaxf(mx, s);
            float corr = __expf(mx - nm);
            float e    = __expf(s - nm);
            sum = sum * corr + e;
            const float* vj = sv + j * 33;
#pragma unroll
            for (int d = 0; d < HDIM; d++) o[d] = o[d] * corr + e * vj[d];
            mx = nm;
        }
        float inv = 1.0f / sum;
        float* op = out + ((size_t)bw * NTOK + tid) * CH + head * HDIM;
#pragma unroll
        for (int d = 0; d < HDIM; d += 4)
            *(float4*)(op + d) = make_float4(o[d] * inv, o[d + 1] * inv,
                                             o[d + 2] * inv, o[d + 3] * inv);
    }
}

// ---------------- launch ------------------------------------------------------
extern "C" void kernel_launch(void* const* d_in, const int* in_sizes, int n_in,
                              void* d_out, int out_size)
{
    const float* x     = (const float*)d_in[0];
    const float* n1g   = (const float*)d_in[1];
    const float* n1b   = (const float*)d_in[2];
    const float* qkvw  = (const float*)d_in[3];
    const float* rpb   = (const float*)d_in[4];
    const float* projw = (const float*)d_in[5];
    const float* projb = (const float*)d_in[6];
    const float* n2g   = (const float*)d_in[7];
    const float* n2b   = (const float*)d_in[8];
    const float* fc1w  = (const float*)d_in[9];
    const float* fc1b  = (const float*)d_in[10];
    const float* fc2w  = (const float*)d_in[11];
    const float* fc2b  = (const float*)d_in[12];
    float* out = (float*)d_out;

    void *pxp, *pxw, *pqkv, *patt, *pxres, *ph2, *pmlp, *py;
    cudaGetSymbolAddress(&pxp,  g_xp);
    cudaGetSymbolAddress(&pxw,  g_xw);
    cudaGetSymbolAddress(&pqkv, g_qkv);
    cudaGetSymbolAddress(&patt, g_att);
    cudaGetSymbolAddress(&pxres,g_xres);
    cudaGetSymbolAddress(&ph2,  g_h2);
    cudaGetSymbolAddress(&pmlp, g_mlp);
    cudaGetSymbolAddress(&py,   g_y);
    float* xp   = (float*)pxp;
    float* xw   = (float*)pxw;
    float* qkv  = (float*)pqkv;
    float* att  = (float*)patt;
    float* xres = (float*)pxres;
    float* h2   = (float*)ph2;
    float* mlp  = (float*)pmlp;
    float* y    = (float*)py;

    dim3 tb(32, 8);
    dim3 tg(24, 84, 16);

    transpose_in_kernel<<<tg, tb>>>(x, xp);
    ln_kernel<true><<<TOK / 8, 256>>>(xp, n1g, n1b, xw);

    tgemm_kernel<0><<<dim3(768 / 128, TOK / 128), 256>>>(xw, qkvw, nullptr, nullptr, qkv, TOK, 768, 256);

    int smem_attn = SMF_TOT * (int)sizeof(float);
    cudaFuncSetAttribute(attn_kernel, cudaFuncAttributeMaxDynamicSharedMemorySize, smem_attn);
    attn_kernel<<<BWIN * NHEAD, 128, smem_attn>>>(qkv, rpb, att);

    tgemm_kernel<1><<<dim3(256 / 128, TOK / 128), 256>>>(att, projw, projb, xp, xres, TOK, 256, 256);

    ln_kernel<false><<<TOK / 8, 256>>>(xres, n2g, n2b, h2);

    tgemm_kernel<2><<<dim3(1024 / 128, TOK / 128), 256>>>(h2, fc1w, fc1b, nullptr, mlp, TOK, 1024, 256);

    tgemm_kernel<3><<<dim3(256 / 128, TOK / 128), 256>>>(mlp, fc2w, fc2b, xres, y, TOK, 256, 1024);

    transpose_out_kernel<<<tg, tb>>>(y, out);
}